// round 7
// baseline (speedup 1.0000x reference)
#include <cuda_runtime.h>
#include <cuda_bf16.h>

// ---------------------------------------------------------------------------
// Decoder_65111704207909  (B=8192, T=20, H=128, K=5)
// Round 7: 1 CTA/SM x 1024 thr (8 warps/SMSP), 56 rows/CTA, grid=147.
//  - thread = (j = tid>>3, g = tid&7): warp spans 4 j x 8 groups
//    -> U LDS.128 = 1 wavefront/warp, h broadcasts amortized across groups
//  - 7 rows/thread: 3 packed f32x2 pairs + 1 scalar row
//  - KCH=16 double-buffered cp.async U staging, 1 barrier per chunk
//  - encW plain [b][col] (bias folded), U gate-interleaved, Wh transposed
// ---------------------------------------------------------------------------

#define Bsz 8192
#define Tt 20
#define Hh 128
#define KcK 5
#define NG 512                    // 4*H
#define ROWS 56
#define NCTA 147
#define NTHREADS 1024
#define HSTR 68                   // phys row stride (272B; group bases 16B-aligned)
#define CSTR 64                   // cond stride
#define KCH 16                    // k-rows per staged chunk
#define NCHUNK (Hh / KCH)         // 8
#define PRE_BB 16

typedef unsigned long long u64;

// enc_h @ W[:H] + b (bias folded): [b][col]
__device__ float g_encW_my[(size_t)Bsz * NG];
__device__ float g_encW_ff[(size_t)Bsz * NG];
// U transposed: [k][j][gate]
__device__ float g_Ut_my[(size_t)Hh * NG];
__device__ float g_Ut_ff[(size_t)Hh * NG];
// Wh transposed: [c][k]
__device__ float g_Wht[75 * Hh];

__device__ __forceinline__ u64 pack2f(float x, float y) {
    u64 r; asm("mov.b64 %0, {%1, %2};" : "=l"(r) : "f"(x), "f"(y)); return r;
}
__device__ __forceinline__ u64 dup2f(float x) {
    u64 r; asm("mov.b64 %0, {%1, %1};" : "=l"(r) : "f"(x)); return r;
}
__device__ __forceinline__ void fma2(u64& d, u64 a, u64 b) {
    asm("fma.rn.f32x2 %0, %1, %2, %0;" : "+l"(d) : "l"(a), "l"(b));
}
__device__ __forceinline__ void unpack2(u64 v, float& x, float& y) {
    asm("mov.b64 {%0, %1}, %2;" : "=f"(x), "=f"(y) : "l"(v));
}

// ---- fast transcendentals ----
__device__ __forceinline__ float ex2f(float x) {
    float y; asm("ex2.approx.f32 %0, %1;" : "=f"(y) : "f"(x)); return y;
}
__device__ __forceinline__ float rcpf(float x) {
    float y; asm("rcp.approx.f32 %0, %1;" : "=f"(y) : "f"(x)); return y;
}
#define LOG2E 1.4426950408889634f
__device__ __forceinline__ float sigf(float x) {
    return rcpf(1.0f + ex2f(-LOG2E * x));
}
__device__ __forceinline__ float tanhf_fast(float x) {
    return fmaf(-2.0f, rcpf(1.0f + ex2f((2.0f * LOG2E) * x)), 1.0f);
}
__device__ __forceinline__ float expf_fast(float x) { return ex2f(LOG2E * x); }

// logical row r (0..55) -> physical row: groups of 7 at pitch 8
__device__ __forceinline__ int physrow(int r) { return (r / 7) * 8 + (r % 7); }

// ---- cp.async: one chunk = KCH*NG = 8192 floats = 1024 thr x 2 x 16B ----
__device__ __forceinline__ void stage_chunk(float* dst, const float* __restrict__ src, int tid) {
    unsigned smp = (unsigned)__cvta_generic_to_shared(dst);
#pragma unroll
    for (int i = 0; i < 2; i++) {
        asm volatile("cp.async.cg.shared.global [%0], [%1], 16;"
                     :: "r"(smp + (unsigned)((tid + i * NTHREADS) * 16)),
                        "l"(src + (size_t)(tid + i * NTHREADS) * 4)
                     : "memory");
    }
    asm volatile("cp.async.commit_group;" ::: "memory");
}
template <int N>
__device__ __forceinline__ void cp_wait() {
    asm volatile("cp.async.wait_group %0;" :: "n"(N) : "memory");
}

// ---------------------------------------------------------------------------
// Precompute: g_encW = state_h @ W[:H,:] + b (plain layout) + folded transposes
// ---------------------------------------------------------------------------
__global__ __launch_bounds__(256) void precompute_kernel(
    const float* __restrict__ state_h,
    const float* __restrict__ W_my, const float* __restrict__ b_my,
    const float* __restrict__ W_ff, const float* __restrict__ b_ff,
    const float* __restrict__ U_my, const float* __restrict__ U_ff,
    const float* __restrict__ Wh_my, const float* __restrict__ Wh_ff)
{
    const int t = threadIdx.x;

    // folded transposes (blocks 0..255 cover Hh*NG = 65536 elems)
    {
        int gidx = blockIdx.x * 256 + t;
        if (gidx < Hh * NG) {
            int k = gidx >> 9;
            int r = gidx & 511;
            int j = r >> 2, g = r & 3;
            g_Ut_my[gidx] = U_my[(size_t)k * NG + g * 128 + j];
            g_Ut_ff[gidx] = U_ff[(size_t)k * NG + g * 128 + j];
        }
        if (gidx < 75 * Hh) {
            int c = gidx >> 7, k = gidx & 127;
            g_Wht[gidx] = (c < 45) ? Wh_my[(size_t)k * 45 + c]
                                   : Wh_ff[(size_t)k * 30 + (c - 45)];
        }
    }

    __shared__ float hsh[Hh * PRE_BB];  // [k][bb]
    const int b0 = blockIdx.x * PRE_BB;

    for (int idx = t; idx < Hh * PRE_BB; idx += 256) {
        int k = idx / PRE_BB, bb = idx % PRE_BB;
        hsh[idx] = state_h[(size_t)(b0 + bb) * Hh + k];
    }
    __syncthreads();

    const int c0 = 2 * t;
    u64 accm[PRE_BB], accf[PRE_BB];
    u64 bm = pack2f(b_my[c0], b_my[c0 + 1]);
    u64 bf = pack2f(b_ff[c0], b_ff[c0 + 1]);
#pragma unroll
    for (int bb = 0; bb < PRE_BB; bb++) { accm[bb] = bm; accf[bb] = bf; }

    for (int k = 0; k < Hh; k++) {
        u64 wm = *(const u64*)&W_my[(size_t)k * NG + c0];
        u64 wf = *(const u64*)&W_ff[(size_t)k * NG + c0];
#pragma unroll
        for (int bb = 0; bb < PRE_BB; bb++) {
            u64 hh = dup2f(hsh[k * PRE_BB + bb]);
            fma2(accm[bb], hh, wm);
            fma2(accf[bb], hh, wf);
        }
    }
#pragma unroll
    for (int bb = 0; bb < PRE_BB; bb++) {
        int b = b0 + bb;
        *(u64*)&g_encW_my[(size_t)b * NG + c0] = accm[bb];
        *(u64*)&g_encW_ff[(size_t)b * NG + c0] = accf[bb];
    }
}

// ---------------------------------------------------------------------------
// One LSTM update for 56 rows with 1024 threads.
// Thread (j = tid>>3, g = tid&7): gate cols {j,j+128,j+256,j+384},
// logical rows g*7..g*7+6 at phys base g*8 (3 pairs + 1 single).
// ---------------------------------------------------------------------------
template <int NQ>
__device__ __forceinline__ void lstm_phase(
    const float* __restrict__ encW,   // [b][col], bias folded
    const float* __restrict__ Ut,     // [k][j][gate]
    const float* __restrict__ Wg,     // W matrix (tail rows H.. used)
    const float* sh_cond, float* sh_h, float* sh_U,
    float (&c)[7], int j, int gph,    // gph = g*8 phys base
    const int* erow, int tid)
{
    stage_chunk(sh_U, Ut, tid);

    // ---- acc init: encW (bias folded) + cond-tail @ W[H:, :] ----
    u64 acc[4][3];
    float acc_s[4];
#pragma unroll
    for (int g4 = 0; g4 < 4; g4++) {
        const int col = g4 * 128 + j;
        const float* eb = encW + col;
#pragma unroll
        for (int p = 0; p < 3; p++)
            acc[g4][p] = pack2f(eb[(size_t)erow[2 * p] * NG],
                                eb[(size_t)erow[2 * p + 1] * NG]);
        acc_s[g4] = eb[(size_t)erow[6] * NG];
    }
#pragma unroll
    for (int q = 0; q < NQ; q++) {
        const float* cb = sh_cond + q * CSTR + gph;
        u64 cp0 = *(const u64*)(cb);
        u64 cp1 = *(const u64*)(cb + 2);
        u64 cp2 = *(const u64*)(cb + 4);
        float cs = cb[6];
#pragma unroll
        for (int g4 = 0; g4 < 4; g4++) {
            float wv = __ldg(&Wg[(size_t)(Hh + q) * NG + g4 * 128 + j]);
            u64 wd = dup2f(wv);
            fma2(acc[g4][0], cp0, wd);
            fma2(acc[g4][1], cp1, wd);
            fma2(acc[g4][2], cp2, wd);
            acc_s[g4] = fmaf(cs, wv, acc_s[g4]);
        }
    }

    // ---- main GEMM, double buffer, one barrier per chunk ----
    for (int ch = 0; ch < NCHUNK; ch++) {
        cp_wait<0>();
        __syncthreads();   // chunk ch visible; all warps past compute(ch-1)
        if (ch + 1 < NCHUNK)
            stage_chunk(sh_U + ((ch + 1) & 1) * KCH * NG,
                        Ut + (size_t)(ch + 1) * KCH * NG, tid);
        const float* ub = sh_U + (ch & 1) * KCH * NG + 4 * j;
        const float* hb = sh_h + (ch * KCH) * HSTR + gph;
#pragma unroll
        for (int kk = 0; kk < KCH; kk++) {
            float4 uu = *(const float4*)(ub + kk * NG);
            const float* hk = hb + kk * HSTR;
            ulonglong2 h0123 = *(const ulonglong2*)(hk);
            u64 h45 = *(const u64*)(hk + 4);
            float h6 = hk[6];
            u64 u0 = dup2f(uu.x);
            u64 u1 = dup2f(uu.y);
            u64 u2 = dup2f(uu.z);
            u64 u3 = dup2f(uu.w);
            fma2(acc[0][0], h0123.x, u0);
            fma2(acc[0][1], h0123.y, u0);
            fma2(acc[0][2], h45, u0);
            fma2(acc[1][0], h0123.x, u1);
            fma2(acc[1][1], h0123.y, u1);
            fma2(acc[1][2], h45, u1);
            fma2(acc[2][0], h0123.x, u2);
            fma2(acc[2][1], h0123.y, u2);
            fma2(acc[2][2], h45, u2);
            fma2(acc[3][0], h0123.x, u3);
            fma2(acc[3][1], h0123.y, u3);
            fma2(acc[3][2], h45, u3);
            acc_s[0] = fmaf(h6, uu.x, acc_s[0]);
            acc_s[1] = fmaf(h6, uu.y, acc_s[1]);
            acc_s[2] = fmaf(h6, uu.z, acc_s[2]);
            acc_s[3] = fmaf(h6, uu.w, acc_s[3]);
        }
    }
    __syncthreads();  // all threads done reading old sh_h

    // ---- gates; c register-private ----
    float* hw = sh_h + j * HSTR + gph;
#pragma unroll
    for (int p = 0; p < 3; p++) {
        float zi0, zi1, zf0, zf1, zg0, zg1, zo0, zo1;
        unpack2(acc[0][p], zi0, zi1);
        unpack2(acc[1][p], zf0, zf1);
        unpack2(acc[2][p], zg0, zg1);
        unpack2(acc[3][p], zo0, zo1);
        float c20 = sigf(zf0) * c[2 * p]     + sigf(zi0) * tanhf_fast(zg0);
        float c21 = sigf(zf1) * c[2 * p + 1] + sigf(zi1) * tanhf_fast(zg1);
        c[2 * p] = c20; c[2 * p + 1] = c21;
        *(u64*)(hw + 2 * p) =
            pack2f(sigf(zo0) * tanhf_fast(c20), sigf(zo1) * tanhf_fast(c21));
    }
    {
        float c2 = sigf(acc_s[1]) * c[6] + sigf(acc_s[0]) * tanhf_fast(acc_s[2]);
        c[6] = c2;
        hw[6] = sigf(acc_s[3]) * tanhf_fast(c2);
    }
}

// ---------------------------------------------------------------------------
__global__ __launch_bounds__(NTHREADS, 1) void decoder_kernel(
    const float* __restrict__ cond_m, const float* __restrict__ cond_y,
    const float* __restrict__ cond_f, const float* __restrict__ cond_fa,
    const float* __restrict__ state_h, const float* __restrict__ state_c,
    const float* __restrict__ W_my, const float* __restrict__ W_ff,
    const float* __restrict__ bh_my, const float* __restrict__ bh_ff,
    const float* __restrict__ gumbel, const float* __restrict__ znorm,
    float* __restrict__ out)
{
    extern __shared__ float smem[];
    float* sh_U     = smem;                       // 2*KCH*NG = 16384 floats
    float* sh_h_my  = sh_U + 2 * KCH * NG;        // Hh*HSTR
    float* sh_h_ff  = sh_h_my + Hh * HSTR;
    float* sh_cond5 = sh_h_ff + Hh * HSTR;        // [q][CSTR] phys rows
    float* sh_cond2 = sh_cond5 + 5 * CSTR;
    float* sh_r     = sh_cond2 + 2 * CSTR;        // [logical row][76]

    const int tid = threadIdx.x;
    const int rowbase = blockIdx.x * ROWS;
    const int j = tid >> 3;        // 0..127
    const int g = tid & 7;         // 0..7
    const int gph = g * 8;         // phys group base

    // ---- init h and cond ----
    for (int idx = tid; idx < Hh * ROWS; idx += NTHREADS) {
        int k = idx / ROWS, row = idx % ROWS;
        int b = min(rowbase + row, Bsz - 1);
        float hv = state_h[(size_t)b * Hh + k];
        int pr = physrow(row);
        sh_h_my[k * HSTR + pr] = hv;
        sh_h_ff[k * HSTR + pr] = hv;
    }
    if (tid < ROWS) {
        int row = tid;
        int pr = physrow(row);
        int b = min(rowbase + row, Bsz - 1);
        float m0 = cond_m[((size_t)b * Tt) * 2 + 0];
        float m1 = cond_m[((size_t)b * Tt) * 2 + 1];
        float y0 = cond_y[(size_t)b * Tt];
        float f0 = cond_f[(size_t)b * Tt];
        float a0 = cond_fa[(size_t)b * Tt];
        sh_cond5[0 * CSTR + pr] = m0;
        sh_cond5[1 * CSTR + pr] = m1;
        sh_cond5[2 * CSTR + pr] = y0;
        sh_cond5[3 * CSTR + pr] = f0;
        sh_cond5[4 * CSTR + pr] = a0;
        sh_cond2[0 * CSTR + pr] = f0;
        sh_cond2[1 * CSTR + pr] = a0;
    }

    // ---- c state in registers, global row indices ----
    float cmy[7], cff[7];
    int erow[7];
#pragma unroll
    for (int r = 0; r < 7; r++) {
        int b = min(rowbase + g * 7 + r, Bsz - 1);
        erow[r] = b;
        float cv = state_c[(size_t)b * Hh + j];
        cmy[r] = cv; cff[r] = cv;
    }

    // head-phase mapping: 600 active threads, c=tid%75, group=tid/75 (0..7)
    const int hc = tid % 75;
    const int hg = tid / 75;
    const bool hact = tid < 600;
    float hbias = 0.0f;
    if (hact) hbias = (hc < 45) ? bh_my[hc] : bh_ff[hc - 45];

    float* out_gm  = out;
    float* out_gy  = out + (size_t)Bsz * Tt * 30;
    float* out_gf  = out + (size_t)Bsz * Tt * 45;
    float* out_gfa = out + (size_t)Bsz * Tt * 60;

    __syncthreads();

    for (int t = 0; t < Tt; t++) {
        lstm_phase<5>(g_encW_my, g_Ut_my, W_my, sh_cond5, sh_h_my, sh_U, cmy, j, gph, erow, tid);
        lstm_phase<2>(g_encW_ff, g_Ut_ff, W_ff, sh_cond2, sh_h_ff, sh_U, cff, j, gph, erow, tid);
        __syncthreads();  // h_my / h_ff visible

        // ===== heads: Wht LDG.128, h via broadcast LDS =====
        if (hact) {
            const float* hb = ((hc < 45) ? sh_h_my : sh_h_ff) + hg * 8;
            const float4* wr = (const float4*)(g_Wht + hc * Hh);
            u64 a[3];
            float a_s;
            u64 binit = dup2f(hbias);
#pragma unroll
            for (int p = 0; p < 3; p++) a[p] = binit;
            a_s = hbias;
#pragma unroll 4
            for (int k4 = 0; k4 < Hh / 4; k4++) {
                float4 w4 = __ldg(&wr[k4]);
                float wv[4] = { w4.x, w4.y, w4.z, w4.w };
#pragma unroll
                for (int kk = 0; kk < 4; kk++) {
                    const float* hk = hb + (4 * k4 + kk) * HSTR;
                    ulonglong2 h0123 = *(const ulonglong2*)(hk);
                    u64 h45 = *(const u64*)(hk + 4);
                    float h6 = hk[6];
                    u64 wd = dup2f(wv[kk]);
                    fma2(a[0], h0123.x, wd);
                    fma2(a[1], h0123.y, wd);
                    fma2(a[2], h45, wd);
                    a_s = fmaf(h6, wv[kk], a_s);
                }
            }
#pragma unroll
            for (int p = 0; p < 3; p++) {
                float v0, v1;
                unpack2(a[p], v0, v1);
                int row = hg * 7 + 2 * p;      // logical row
                sh_r[row * 76 + hc] = v0;
                sh_r[(row + 1) * 76 + hc] = v1;
            }
            sh_r[(hg * 7 + 6) * 76 + hc] = a_s;
        }
        __syncthreads();

        // ===== sampling / cond update / outputs =====
        if (tid < 4 * ROWS) {
            const int row = tid >> 2;          // logical row
            const int pr = physrow(row);
            const int d = tid & 3;
            const bool valid = (rowbase + row) < Bsz;
            const int b = min(rowbase + row, Bsz - 1);
            const int tn = min(t + 1, Tt - 1);
            const float* gum = gumbel + (((size_t)t * 4 + d) * Bsz + b) * KcK;
            const float* zn = znorm + ((size_t)t * Bsz + b) * 5;

            if (d == 0) {
                const float* rb = sh_r + row * 76;
                float lg[5], mul[5], sl[5], mulat[5], slat[5], rho[5];
#pragma unroll
                for (int k = 0; k < 5; k++) {
                    lg[k]    = rb[k];
                    mul[k]   = rb[5 + k];
                    sl[k]    = expf_fast(rb[10 + k]);
                    mulat[k] = rb[15 + k];
                    slat[k]  = expf_fast(rb[20 + k]);
                    rho[k]   = tanhf_fast(rb[25 + k]);
                }
                float mx = lg[0];
#pragma unroll
                for (int k = 1; k < 5; k++) mx = fmaxf(mx, lg[k]);
                float am[5], ssum = 0.0f;
#pragma unroll
                for (int k = 0; k < 5; k++) { am[k] = expf_fast(lg[k] - mx); ssum += am[k]; }
                float inv = 1.0f / ssum;
#pragma unroll
                for (int k = 0; k < 5; k++) am[k] *= inv;
                int im = 0; float best = lg[0] + gum[0];
#pragma unroll
                for (int k = 1; k < 5; k++) {
                    float v = lg[k] + gum[k];
                    if (v > best) { best = v; im = k; }
                }
                float z1 = zn[0], z2 = zn[1];
                float rr = rho[im];
                float s_long = mul[im] + sl[im] * z1;
                float s_lt = mulat[im] + slat[im] * (rr * z1 + sqrtf(fmaxf(1.0f - rr * rr, 0.0f)) * z2);
                float nm0 = cond_m[((size_t)b * Tt + tn) * 2 + 0];
                float nm1 = cond_m[((size_t)b * Tt + tn) * 2 + 1];
                sh_cond5[0 * CSTR + pr] = (fabsf(s_long - nm0) < 0.3f) ? s_long : nm0;
                sh_cond5[1 * CSTR + pr] = (fabsf(s_lt  - nm1) < 0.1f) ? s_lt  : nm1;
                if (valid) {
                    float* o = out_gm + ((size_t)b * Tt + t) * 30;
#pragma unroll
                    for (int k = 0; k < 5; k++) {
                        o[k] = am[k]; o[5 + k] = mul[k]; o[10 + k] = sl[k];
                        o[15 + k] = mulat[k]; o[20 + k] = slat[k]; o[25 + k] = rho[k];
                    }
                }
            } else {
                const float* rb;
                float zv, nv;
                float* osec;
                if (d == 1) {
                    rb = sh_r + row * 76 + 30; zv = zn[2];
                    nv = cond_y[(size_t)b * Tt + tn]; osec = out_gy;
                } else if (d == 2) {
                    rb = sh_r + row * 76 + 45; zv = zn[3];
                    nv = cond_f[(size_t)b * Tt + tn]; osec = out_gf;
                } else {
                    rb = sh_r + row * 76 + 60; zv = zn[4];
                    nv = cond_fa[(size_t)b * Tt + tn]; osec = out_gfa;
                }
                float lg[5], mu[5], s[5];
#pragma unroll
                for (int k = 0; k < 5; k++) {
                    lg[k] = rb[k]; mu[k] = rb[5 + k]; s[k] = expf_fast(rb[10 + k]);
                }
                float mx = lg[0];
#pragma unroll
                for (int k = 1; k < 5; k++) mx = fmaxf(mx, lg[k]);
                float am[5], ssum = 0.0f;
#pragma unroll
                for (int k = 0; k < 5; k++) { am[k] = expf_fast(lg[k] - mx); ssum += am[k]; }
                float inv = 1.0f / ssum;
#pragma unroll
                for (int k = 0; k < 5; k++) am[k] *= inv;
                int im = 0; float best = lg[0] + gum[0];
#pragma unroll
                for (int k = 1; k < 5; k++) {
                    float v = lg[k] + gum[k];
                    if (v > best) { best = v; im = k; }
                }
                float samp = mu[im] + s[im] * zv;
                float cn = (fabsf(samp - nv) < 0.3f) ? samp : nv;
                if (d == 1) {
                    sh_cond5[2 * CSTR + pr] = cn;
                } else if (d == 2) {
                    sh_cond5[3 * CSTR + pr] = cn;
                    sh_cond2[0 * CSTR + pr] = cn;
                } else {
                    sh_cond5[4 * CSTR + pr] = cn;
                    sh_cond2[1 * CSTR + pr] = cn;
                }
                if (valid) {
                    float* o = osec + ((size_t)b * Tt + t) * 15;
#pragma unroll
                    for (int k = 0; k < 5; k++) {
                        o[k] = am[k]; o[5 + k] = mu[k]; o[10 + k] = s[k];
                    }
                }
            }
        }
        __syncthreads();  // cond updated for next step
    }
}

// ---------------------------------------------------------------------------
extern "C" void kernel_launch(void* const* d_in, const int* in_sizes, int n_in,
                              void* d_out, int out_size)
{
    (void)in_sizes; (void)n_in; (void)out_size;
    const float* cond_m  = (const float*)d_in[0];
    const float* cond_y  = (const float*)d_in[1];
    const float* cond_f  = (const float*)d_in[2];
    const float* cond_fa = (const float*)d_in[3];
    const float* state_h = (const float*)d_in[4];
    const float* state_c = (const float*)d_in[5];
    const float* W_my    = (const float*)d_in[6];
    const float* U_my    = (const float*)d_in[7];
    const float* b_my    = (const float*)d_in[8];
    const float* W_ff    = (const float*)d_in[9];
    const float* U_ff    = (const float*)d_in[10];
    const float* b_ff    = (const float*)d_in[11];
    const float* Wh_my   = (const float*)d_in[12];
    const float* bh_my   = (const float*)d_in[13];
    const float* Wh_ff   = (const float*)d_in[14];
    const float* bh_ff   = (const float*)d_in[15];
    const float* gumbel  = (const float*)d_in[16];
    const float* znorm   = (const float*)d_in[17];
    float* out = (float*)d_out;

    const int smem_floats = 2 * KCH * NG + 2 * Hh * HSTR + 7 * CSTR + ROWS * 76;
    const int smem_bytes = smem_floats * (int)sizeof(float);  // ~154 KB

    cudaFuncSetAttribute(decoder_kernel,
                         cudaFuncAttributeMaxDynamicSharedMemorySize, smem_bytes);

    precompute_kernel<<<Bsz / PRE_BB, 256>>>(state_h, W_my, b_my, W_ff, b_ff,
                                             U_my, U_ff, Wh_my, Wh_ff);
    decoder_kernel<<<NCTA, NTHREADS, smem_bytes>>>(
        cond_m, cond_y, cond_f, cond_fa, state_h, state_c,
        W_my, W_ff, bh_my, bh_ff, gumbel, znorm, out);
}

// round 8
// speedup vs baseline: 1.8048x; 1.8048x over previous
#include <cuda_runtime.h>
#include <cuda_bf16.h>

// ---------------------------------------------------------------------------
// Decoder_65111704207909  (B=8192, T=20, H=128, K=5)
// Round 8: R6 config (1 CTA/SM x 512 thr, 56 rows, grid=147) + phase attack:
//  - tanh.approx.f32 HW MUFU: gates 10 -> 5 MUFU/row
//  - KCH=32: 5 barriers/phase (was 9); 13 barriers/step total
//  - sampling inputs (gumbel/znorm/cond-next) prefetched before GEMMs
// ---------------------------------------------------------------------------

#define Bsz 8192
#define Tt 20
#define Hh 128
#define KcK 5
#define NG 512                    // 4*H
#define ROWS 56
#define NCTA 147
#define NTHREADS 512
#define HSTR 68                   // phys row stride (272B; group bases 16B-aligned)
#define CSTR 64                   // cond stride
#define KCH 32                    // k-rows per staged chunk
#define NCHUNK (Hh / KCH)         // 4
#define PRE_BB 16

typedef unsigned long long u64;

// enc_h @ W[:H] + b (bias folded), pair-packed: [(b>>1)][col][b&1]
__device__ float g_encW_my[(size_t)Bsz * NG];
__device__ float g_encW_ff[(size_t)Bsz * NG];
// U transposed: [k][j][gate]
__device__ float g_Ut_my[(size_t)Hh * NG];
__device__ float g_Ut_ff[(size_t)Hh * NG];
// Wh transposed: [c][k]
__device__ float g_Wht[75 * Hh];

__device__ __forceinline__ u64 pack2f(float x, float y) {
    u64 r; asm("mov.b64 %0, {%1, %2};" : "=l"(r) : "f"(x), "f"(y)); return r;
}
__device__ __forceinline__ u64 dup2f(float x) {
    u64 r; asm("mov.b64 %0, {%1, %1};" : "=l"(r) : "f"(x)); return r;
}
__device__ __forceinline__ void fma2(u64& d, u64 a, u64 b) {
    asm("fma.rn.f32x2 %0, %1, %2, %0;" : "+l"(d) : "l"(a), "l"(b));
}
__device__ __forceinline__ void unpack2(u64 v, float& x, float& y) {
    asm("mov.b64 {%0, %1}, %2;" : "=f"(x), "=f"(y) : "l"(v));
}

// ---- fast transcendentals ----
__device__ __forceinline__ float ex2f(float x) {
    float y; asm("ex2.approx.f32 %0, %1;" : "=f"(y) : "f"(x)); return y;
}
#define LOG2E 1.4426950408889634f
__device__ __forceinline__ float tanh_hw(float x) {
    float y; asm("tanh.approx.f32 %0, %1;" : "=f"(y) : "f"(x)); return y;
}
__device__ __forceinline__ float sigf(float x) {
    return fmaf(0.5f, tanh_hw(0.5f * x), 0.5f);   // 1 MUFU + 2 FMA
}
__device__ __forceinline__ float expf_fast(float x) { return ex2f(LOG2E * x); }

// logical row r (0..55) -> physical row: groups of 14 at pitch 16
__device__ __forceinline__ int physrow(int r) { return (r / 14) * 16 + (r % 14); }

// ---- cp.async: one chunk = KCH*NG = 16384 floats = 512 thr x 8 x 16B ----
__device__ __forceinline__ void stage_chunk(float* dst, const float* __restrict__ src, int tid) {
    unsigned smp = (unsigned)__cvta_generic_to_shared(dst);
#pragma unroll
    for (int i = 0; i < 8; i++) {
        asm volatile("cp.async.cg.shared.global [%0], [%1], 16;"
                     :: "r"(smp + (unsigned)((tid + i * NTHREADS) * 16)),
                        "l"(src + (size_t)(tid + i * NTHREADS) * 4)
                     : "memory");
    }
    asm volatile("cp.async.commit_group;" ::: "memory");
}
template <int N>
__device__ __forceinline__ void cp_wait() {
    asm volatile("cp.async.wait_group %0;" :: "n"(N) : "memory");
}

// ---------------------------------------------------------------------------
// Precompute: g_encW = state_h @ W[:H,:] + b (pair-packed) + folded transposes
// ---------------------------------------------------------------------------
__global__ __launch_bounds__(256) void precompute_kernel(
    const float* __restrict__ state_h,
    const float* __restrict__ W_my, const float* __restrict__ b_my,
    const float* __restrict__ W_ff, const float* __restrict__ b_ff,
    const float* __restrict__ U_my, const float* __restrict__ U_ff,
    const float* __restrict__ Wh_my, const float* __restrict__ Wh_ff)
{
    const int t = threadIdx.x;

    // folded transposes (blocks 0..255 cover Hh*NG = 65536 elems)
    {
        int gidx = blockIdx.x * 256 + t;
        if (gidx < Hh * NG) {
            int k = gidx >> 9;
            int r = gidx & 511;
            int j = r >> 2, g = r & 3;
            g_Ut_my[gidx] = U_my[(size_t)k * NG + g * 128 + j];
            g_Ut_ff[gidx] = U_ff[(size_t)k * NG + g * 128 + j];
        }
        if (gidx < 75 * Hh) {
            int c = gidx >> 7, k = gidx & 127;
            g_Wht[gidx] = (c < 45) ? Wh_my[(size_t)k * 45 + c]
                                   : Wh_ff[(size_t)k * 30 + (c - 45)];
        }
    }

    __shared__ float hsh[Hh * PRE_BB];  // [k][bb]
    const int b0 = blockIdx.x * PRE_BB;

    for (int idx = t; idx < Hh * PRE_BB; idx += 256) {
        int k = idx / PRE_BB, bb = idx % PRE_BB;
        hsh[idx] = state_h[(size_t)(b0 + bb) * Hh + k];
    }
    __syncthreads();

    const int c0 = 2 * t;
    u64 accm[PRE_BB], accf[PRE_BB];
    u64 bm = pack2f(b_my[c0], b_my[c0 + 1]);
    u64 bf = pack2f(b_ff[c0], b_ff[c0 + 1]);
#pragma unroll
    for (int bb = 0; bb < PRE_BB; bb++) { accm[bb] = bm; accf[bb] = bf; }

    for (int k = 0; k < Hh; k++) {
        u64 wm = *(const u64*)&W_my[(size_t)k * NG + c0];
        u64 wf = *(const u64*)&W_ff[(size_t)k * NG + c0];
#pragma unroll
        for (int bb = 0; bb < PRE_BB; bb++) {
            u64 hh = dup2f(hsh[k * PRE_BB + bb]);
            fma2(accm[bb], hh, wm);
            fma2(accf[bb], hh, wf);
        }
    }
    // pair-packed store: idx = ((b>>1)*NG + col)*2 + (b&1)
#pragma unroll
    for (int bb = 0; bb < PRE_BB; bb++) {
        int b = b0 + bb;
        size_t base = ((size_t)(b >> 1) * NG) * 2 + (b & 1);
        float v0, v1;
        unpack2(accm[bb], v0, v1);
        g_encW_my[base + 2 * (size_t)c0] = v0;
        g_encW_my[base + 2 * (size_t)(c0 + 1)] = v1;
        unpack2(accf[bb], v0, v1);
        g_encW_ff[base + 2 * (size_t)c0] = v0;
        g_encW_ff[base + 2 * (size_t)(c0 + 1)] = v1;
    }
}

// ---------------------------------------------------------------------------
// One LSTM update for 56 rows with 512 threads.
// Thread (j = tid&127, g = tid>>7): gate cols {j,j+128,j+256,j+384},
// logical rows g*14..g*14+13 at phys base g*16 (7 packed row-pairs).
// ---------------------------------------------------------------------------
template <int NQ>
__device__ __forceinline__ void lstm_phase(
    const float* __restrict__ encW,   // pair-packed
    const float* __restrict__ Ut,     // gate-interleaved [k][j][gate]
    const float* __restrict__ Wg,     // W matrix (tail rows H.. used)
    const float* sh_cond, float* sh_h, float* sh_U,
    float (&c)[14], int j, int rphys, const int* epair, int tid)
{
    stage_chunk(sh_U, Ut, tid);

    // ---- acc init: encW (bias folded, LDG.64) + cond-tail @ W[H:, :] ----
    u64 acc[4][7];
#pragma unroll
    for (int g4 = 0; g4 < 4; g4++) {
        const int col = g4 * 128 + j;
#pragma unroll
        for (int p = 0; p < 7; p++)
            acc[g4][p] = *(const u64*)&encW[((size_t)epair[p] * NG + col) * 2];
    }
#pragma unroll
    for (int q = 0; q < NQ; q++) {
        u64 cpp[7];
#pragma unroll
        for (int p = 0; p < 7; p++)
            cpp[p] = *(const u64*)(sh_cond + q * CSTR + rphys + 2 * p);
#pragma unroll
        for (int g4 = 0; g4 < 4; g4++) {
            u64 wd = dup2f(__ldg(&Wg[(size_t)(Hh + q) * NG + g4 * 128 + j]));
#pragma unroll
            for (int p = 0; p < 7; p++) fma2(acc[g4][p], cpp[p], wd);
        }
    }

    // ---- main GEMM, double buffer, one barrier per chunk ----
    for (int ch = 0; ch < NCHUNK; ch++) {
        cp_wait<0>();
        __syncthreads();   // chunk ch visible; all warps past compute(ch-1)
        if (ch + 1 < NCHUNK)
            stage_chunk(sh_U + ((ch + 1) & 1) * KCH * NG,
                        Ut + (size_t)(ch + 1) * KCH * NG, tid);
        const float* ub = sh_U + (ch & 1) * KCH * NG + 4 * j;
        const float* hb = sh_h + (ch * KCH) * HSTR + rphys;
#pragma unroll
        for (int kk = 0; kk < KCH; kk++) {
            float4 uu = *(const float4*)(ub + kk * NG);
            u64 u0 = dup2f(uu.x);
            u64 u1 = dup2f(uu.y);
            u64 u2 = dup2f(uu.z);
            u64 u3 = dup2f(uu.w);
            const float* hk = hb + kk * HSTR;
            ulonglong2 h01 = *(const ulonglong2*)(hk);
            ulonglong2 h23 = *(const ulonglong2*)(hk + 4);
            ulonglong2 h45 = *(const ulonglong2*)(hk + 8);
            u64 h6 = *(const u64*)(hk + 12);
            u64 hp[7] = { h01.x, h01.y, h23.x, h23.y, h45.x, h45.y, h6 };
#pragma unroll
            for (int p = 0; p < 7; p++) {
                u64 h2 = hp[p];
                fma2(acc[0][p], h2, u0);
                fma2(acc[1][p], h2, u1);
                fma2(acc[2][p], h2, u2);
                fma2(acc[3][p], h2, u3);
            }
        }
    }
    __syncthreads();  // all threads done reading old sh_h

    // ---- gates; c register-private; HW tanh ----
#pragma unroll
    for (int p = 0; p < 7; p++) {
        float zi0, zi1, zf0, zf1, zg0, zg1, zo0, zo1;
        unpack2(acc[0][p], zi0, zi1);
        unpack2(acc[1][p], zf0, zf1);
        unpack2(acc[2][p], zg0, zg1);
        unpack2(acc[3][p], zo0, zo1);
        float c20 = sigf(zf0) * c[2 * p]     + sigf(zi0) * tanh_hw(zg0);
        float c21 = sigf(zf1) * c[2 * p + 1] + sigf(zi1) * tanh_hw(zg1);
        c[2 * p] = c20; c[2 * p + 1] = c21;
        *(u64*)(sh_h + j * HSTR + rphys + 2 * p) =
            pack2f(sigf(zo0) * tanh_hw(c20), sigf(zo1) * tanh_hw(c21));
    }
}

// ---------------------------------------------------------------------------
__global__ __launch_bounds__(NTHREADS, 1) void decoder_kernel(
    const float* __restrict__ cond_m, const float* __restrict__ cond_y,
    const float* __restrict__ cond_f, const float* __restrict__ cond_fa,
    const float* __restrict__ state_h, const float* __restrict__ state_c,
    const float* __restrict__ W_my, const float* __restrict__ W_ff,
    const float* __restrict__ bh_my, const float* __restrict__ bh_ff,
    const float* __restrict__ gumbel, const float* __restrict__ znorm,
    float* __restrict__ out)
{
    extern __shared__ float smem[];
    float* sh_U     = smem;                       // 2*KCH*NG = 32768 floats
    float* sh_h_my  = sh_U + 2 * KCH * NG;        // Hh*HSTR
    float* sh_h_ff  = sh_h_my + Hh * HSTR;
    float* sh_cond5 = sh_h_ff + Hh * HSTR;        // [q][CSTR] phys rows
    float* sh_cond2 = sh_cond5 + 5 * CSTR;
    float* sh_r     = sh_cond2 + 2 * CSTR;        // [logical row][76]

    const int tid = threadIdx.x;
    const int rowbase = blockIdx.x * ROWS;
    const int j = tid & 127;
    const int g = tid >> 7;        // 0..3
    const int rlog = g * 14;
    const int rphys = g * 16;

    // ---- init h and cond ----
    for (int idx = tid; idx < Hh * ROWS; idx += NTHREADS) {
        int k = idx / ROWS, row = idx % ROWS;
        int b = min(rowbase + row, Bsz - 1);
        float hv = state_h[(size_t)b * Hh + k];
        int pr = physrow(row);
        sh_h_my[k * HSTR + pr] = hv;
        sh_h_ff[k * HSTR + pr] = hv;
    }
    if (tid < ROWS) {
        int row = tid;
        int pr = physrow(row);
        int b = min(rowbase + row, Bsz - 1);
        float m0 = cond_m[((size_t)b * Tt) * 2 + 0];
        float m1 = cond_m[((size_t)b * Tt) * 2 + 1];
        float y0 = cond_y[(size_t)b * Tt];
        float f0 = cond_f[(size_t)b * Tt];
        float a0 = cond_fa[(size_t)b * Tt];
        sh_cond5[0 * CSTR + pr] = m0;
        sh_cond5[1 * CSTR + pr] = m1;
        sh_cond5[2 * CSTR + pr] = y0;
        sh_cond5[3 * CSTR + pr] = f0;
        sh_cond5[4 * CSTR + pr] = a0;
        sh_cond2[0 * CSTR + pr] = f0;
        sh_cond2[1 * CSTR + pr] = a0;
    }

    // ---- c state in registers, encW pair indices (logical rows) ----
    float cmy[14], cff[14];
    int epair[7];
#pragma unroll
    for (int r = 0; r < 14; r++) {
        int b = min(rowbase + rlog + r, Bsz - 1);
        float cv = state_c[(size_t)b * Hh + j];
        cmy[r] = cv; cff[r] = cv;
    }
#pragma unroll
    for (int p = 0; p < 7; p++)
        epair[p] = min(rowbase + rlog + 2 * p, Bsz - 2) >> 1;

    // head-phase mapping: 300 active threads, c=tid%75, quarter=tid/75
    const int hc = tid % 75;
    const int hq = tid / 75;       // 0..3 row group
    const bool hact = tid < 300;
    float hbias = 0.0f;
    if (hact) hbias = (hc < 45) ? bh_my[hc] : bh_ff[hc - 45];

    // sampling-thread constants
    const int s_row = tid >> 2;
    const int s_d = tid & 3;
    const bool s_act = tid < 4 * ROWS;
    const int s_b = s_act ? min(rowbase + s_row, Bsz - 1) : 0;
    const bool s_valid = s_act && (rowbase + s_row) < Bsz;

    float* out_gm  = out;
    float* out_gy  = out + (size_t)Bsz * Tt * 30;
    float* out_gf  = out + (size_t)Bsz * Tt * 45;
    float* out_gfa = out + (size_t)Bsz * Tt * 60;

    __syncthreads();

    for (int t = 0; t < Tt; t++) {
        // ---- prefetch sampling inputs; latency hides under both GEMMs ----
        float pg[5], pz1 = 0.f, pz2 = 0.f, pn1 = 0.f, pn2 = 0.f;
        if (s_act) {
            const int tn = min(t + 1, Tt - 1);
            const float* gum = gumbel + (((size_t)t * 4 + s_d) * Bsz + s_b) * KcK;
            const float* zn = znorm + ((size_t)t * Bsz + s_b) * 5;
#pragma unroll
            for (int k = 0; k < 5; k++) pg[k] = __ldg(gum + k);
            if (s_d == 0) {
                pz1 = __ldg(zn + 0); pz2 = __ldg(zn + 1);
                pn1 = __ldg(&cond_m[((size_t)s_b * Tt + tn) * 2 + 0]);
                pn2 = __ldg(&cond_m[((size_t)s_b * Tt + tn) * 2 + 1]);
            } else if (s_d == 1) {
                pz1 = __ldg(zn + 2); pn1 = __ldg(&cond_y[(size_t)s_b * Tt + tn]);
            } else if (s_d == 2) {
                pz1 = __ldg(zn + 3); pn1 = __ldg(&cond_f[(size_t)s_b * Tt + tn]);
            } else {
                pz1 = __ldg(zn + 4); pn1 = __ldg(&cond_fa[(size_t)s_b * Tt + tn]);
            }
        }

        lstm_phase<5>(g_encW_my, g_Ut_my, W_my, sh_cond5, sh_h_my, sh_U, cmy, j, rphys, epair, tid);
        lstm_phase<2>(g_encW_ff, g_Ut_ff, W_ff, sh_cond2, sh_h_ff, sh_U, cff, j, rphys, epair, tid);
        __syncthreads();  // h_my / h_ff visible

        // ===== heads: Wht LDG.128, h via broadcast LDS.128 =====
        if (hact) {
            const float* hb = ((hc < 45) ? sh_h_my : sh_h_ff) + hq * 16;
            const float4* wr = (const float4*)(g_Wht + hc * Hh);
            u64 a[7];
            u64 binit = dup2f(hbias);
#pragma unroll
            for (int p = 0; p < 7; p++) a[p] = binit;
#pragma unroll 4
            for (int k4 = 0; k4 < Hh / 4; k4++) {
                float4 w4 = __ldg(&wr[k4]);
                float wv[4] = { w4.x, w4.y, w4.z, w4.w };
#pragma unroll
                for (int kk = 0; kk < 4; kk++) {
                    const float* hk = hb + (4 * k4 + kk) * HSTR;
                    ulonglong2 h01 = *(const ulonglong2*)(hk);
                    ulonglong2 h23 = *(const ulonglong2*)(hk + 4);
                    ulonglong2 h45 = *(const ulonglong2*)(hk + 8);
                    u64 h6 = *(const u64*)(hk + 12);
                    u64 wd = dup2f(wv[kk]);
                    fma2(a[0], h01.x, wd);
                    fma2(a[1], h01.y, wd);
                    fma2(a[2], h23.x, wd);
                    fma2(a[3], h23.y, wd);
                    fma2(a[4], h45.x, wd);
                    fma2(a[5], h45.y, wd);
                    fma2(a[6], h6, wd);
                }
            }
#pragma unroll
            for (int p = 0; p < 7; p++) {
                float v0, v1;
                unpack2(a[p], v0, v1);
                int row = hq * 14 + 2 * p;     // logical row
                sh_r[row * 76 + hc] = v0;
                sh_r[(row + 1) * 76 + hc] = v1;
            }
        }
        __syncthreads();

        // ===== sampling / cond update / outputs =====
        if (s_act) {
            const int row = s_row;
            const int pr = physrow(row);
            const int d = s_d;
            const int b = s_b;

            if (d == 0) {
                const float* rb = sh_r + row * 76;
                float lg[5], mul[5], sl[5], mulat[5], slat[5], rho[5];
#pragma unroll
                for (int k = 0; k < 5; k++) {
                    lg[k]    = rb[k];
                    mul[k]   = rb[5 + k];
                    sl[k]    = expf_fast(rb[10 + k]);
                    mulat[k] = rb[15 + k];
                    slat[k]  = expf_fast(rb[20 + k]);
                    rho[k]   = tanh_hw(rb[25 + k]);
                }
                float mx = lg[0];
#pragma unroll
                for (int k = 1; k < 5; k++) mx = fmaxf(mx, lg[k]);
                float am[5], ssum = 0.0f;
#pragma unroll
                for (int k = 0; k < 5; k++) { am[k] = expf_fast(lg[k] - mx); ssum += am[k]; }
                float inv = 1.0f / ssum;
#pragma unroll
                for (int k = 0; k < 5; k++) am[k] *= inv;
                int im = 0; float best = lg[0] + pg[0];
#pragma unroll
                for (int k = 1; k < 5; k++) {
                    float v = lg[k] + pg[k];
                    if (v > best) { best = v; im = k; }
                }
                float rr = rho[im];
                float s_long = mul[im] + sl[im] * pz1;
                float s_lt = mulat[im] + slat[im] * (rr * pz1 + sqrtf(fmaxf(1.0f - rr * rr, 0.0f)) * pz2);
                sh_cond5[0 * CSTR + pr] = (fabsf(s_long - pn1) < 0.3f) ? s_long : pn1;
                sh_cond5[1 * CSTR + pr] = (fabsf(s_lt  - pn2) < 0.1f) ? s_lt  : pn2;
                if (s_valid) {
                    float* o = out_gm + ((size_t)b * Tt + t) * 30;
#pragma unroll
                    for (int k = 0; k < 5; k++) {
                        o[k] = am[k]; o[5 + k] = mul[k]; o[10 + k] = sl[k];
                        o[15 + k] = mulat[k]; o[20 + k] = slat[k]; o[25 + k] = rho[k];
                    }
                }
            } else {
                const float* rb;
                float* osec;
                if (d == 1)      { rb = sh_r + row * 76 + 30; osec = out_gy; }
                else if (d == 2) { rb = sh_r + row * 76 + 45; osec = out_gf; }
                else             { rb = sh_r + row * 76 + 60; osec = out_gfa; }
                float lg[5], mu[5], s[5];
#pragma unroll
                for (int k = 0; k < 5; k++) {
                    lg[k] = rb[k]; mu[k] = rb[5 + k]; s[k] = expf_fast(rb[10 + k]);
                }
                float mx = lg[0];
#pragma unroll
                for (int k = 1; k < 5; k++) mx = fmaxf(mx, lg[k]);
                float am[5], ssum = 0.0f;
#pragma unroll
                for (int k = 0; k < 5; k++) { am[k] = expf_fast(lg[k] - mx); ssum += am[k]; }
                float inv = 1.0f / ssum;
#pragma unroll
                for (int k = 0; k < 5; k++) am[k] *= inv;
                int im = 0; float best = lg[0] + pg[0];
#pragma unroll
                for (int k = 1; k < 5; k++) {
                    float v = lg[k] + pg[k];
                    if (v > best) { best = v; im = k; }
                }
                float samp = mu[im] + s[im] * pz1;
                float cn = (fabsf(samp - pn1) < 0.3f) ? samp : pn1;
                if (d == 1) {
                    sh_cond5[2 * CSTR + pr] = cn;
                } else if (d == 2) {
                    sh_cond5[3 * CSTR + pr] = cn;
                    sh_cond2[0 * CSTR + pr] = cn;
                } else {
                    sh_cond5[4 * CSTR + pr] = cn;
                    sh_cond2[1 * CSTR + pr] = cn;
                }
                if (s_valid) {
                    float* o = osec + ((size_t)b * Tt + t) * 15;
#pragma unroll
                    for (int k = 0; k < 5; k++) {
                        o[k] = am[k]; o[5 + k] = mu[k]; o[10 + k] = s[k];
                    }
                }
            }
        }
        __syncthreads();  // cond updated for next step
    }
}

// ---------------------------------------------------------------------------
extern "C" void kernel_launch(void* const* d_in, const int* in_sizes, int n_in,
                              void* d_out, int out_size)
{
    (void)in_sizes; (void)n_in; (void)out_size;
    const float* cond_m  = (const float*)d_in[0];
    const float* cond_y  = (const float*)d_in[1];
    const float* cond_f  = (const float*)d_in[2];
    const float* cond_fa = (const float*)d_in[3];
    const float* state_h = (const float*)d_in[4];
    const float* state_c = (const float*)d_in[5];
    const float* W_my    = (const float*)d_in[6];
    const float* U_my    = (const float*)d_in[7];
    const float* b_my    = (const float*)d_in[8];
    const float* W_ff    = (const float*)d_in[9];
    const float* U_ff    = (const float*)d_in[10];
    const float* b_ff    = (const float*)d_in[11];
    const float* Wh_my   = (const float*)d_in[12];
    const float* bh_my   = (const float*)d_in[13];
    const float* Wh_ff   = (const float*)d_in[14];
    const float* bh_ff   = (const float*)d_in[15];
    const float* gumbel  = (const float*)d_in[16];
    const float* znorm   = (const float*)d_in[17];
    float* out = (float*)d_out;

    const int smem_floats = 2 * KCH * NG + 2 * Hh * HSTR + 7 * CSTR + ROWS * 76;
    const int smem_bytes = smem_floats * (int)sizeof(float);  // ~219.5 KB

    cudaFuncSetAttribute(decoder_kernel,
                         cudaFuncAttributeMaxDynamicSharedMemorySize, smem_bytes);

    precompute_kernel<<<Bsz / PRE_BB, 256>>>(state_h, W_my, b_my, W_ff, b_ff,
                                             U_my, U_ff, Wh_my, Wh_ff);
    decoder_kernel<<<NCTA, NTHREADS, smem_bytes>>>(
        cond_m, cond_y, cond_f, cond_fa, state_h, state_c,
        W_my, W_ff, bh_my, bh_ff, gumbel, znorm, out);
}